// round 8
// baseline (speedup 1.0000x reference)
#include <cuda_runtime.h>
#include <math.h>

#define BB 64
#define SS 1024
#define DD 256
#define NLAYERS 8
#define KANH 32
#define NCLS 1000
#define EPSF 1e-8f
#define PI_F 3.14159265358979323846f
#define NCHUNK 16          /* S split into 16 chunks of 64 rows for deterministic partial sums */
#define BD (BB*DD)         /* 16384 */

// ---------------- persistent device scratch (no allocations allowed) ----------------
__device__ float g_xc[BB*SS*DD];      // also holds h1 right after GEMM
__device__ float g_yc[BB*SS*DD];      // also holds h2 right after GEMM
__device__ float g_xp[NCHUNK*BD];     // per-chunk partial sums of xc  (or r on last layer)
__device__ float g_yp[NCHUNK*BD];     // per-chunk partial sums of yc
__device__ float g_dx[BD];            // per-(b,d) layer offset x
__device__ float g_dy[BD];            // per-(b,d) layer offset y

__device__ __forceinline__ float gelu_exact(float v) {
    return 0.5f * v * (1.0f + erff(v * 0.70710678118654752440f));
}

// ---------------- 1) embed GEMM:  H[65536,512] = X[65536,256] @ W[256,512] + b ----------------
// cols [0,256) -> g_xc (h1), cols [256,512) -> g_yc (h2)
// Tiles: BM=128, BN=64, BK=16; 256 threads; 8x4 per-thread register tile.
__global__ __launch_bounds__(256) void k_embed_gemm(const float* __restrict__ A,
                                                    const float* __restrict__ W,
                                                    const float* __restrict__ bias) {
    __shared__ float As[16][128];   // transposed: As[k][m]
    __shared__ float Bs[16][64];

    const int tid  = threadIdx.x;
    const int bm   = blockIdx.y * 128;
    const int bn   = blockIdx.x * 64;
    const int tx   = tid & 15;          // 16 thread-cols * 4
    const int ty   = tid >> 4;          // 16 thread-rows * 8
    const int arow = tid >> 2;          // 0..63 (and +64)
    const int acol = (tid & 3) << 2;    // 0,4,8,12
    const int bkr  = tid >> 4;          // 0..15
    const int bc   = (tid & 15) << 2;   // 0..60

    float acc[8][4];
#pragma unroll
    for (int j = 0; j < 8; j++)
#pragma unroll
        for (int l = 0; l < 4; l++) acc[j][l] = 0.0f;

    for (int k0 = 0; k0 < 256; k0 += 16) {
        float4 a0 = *(const float4*)(A + (size_t)(bm + arow)      * 256 + k0 + acol);
        float4 a1 = *(const float4*)(A + (size_t)(bm + arow + 64) * 256 + k0 + acol);
        As[acol + 0][arow]      = a0.x; As[acol + 1][arow]      = a0.y;
        As[acol + 2][arow]      = a0.z; As[acol + 3][arow]      = a0.w;
        As[acol + 0][arow + 64] = a1.x; As[acol + 1][arow + 64] = a1.y;
        As[acol + 2][arow + 64] = a1.z; As[acol + 3][arow + 64] = a1.w;
        *(float4*)&Bs[bkr][bc] = *(const float4*)(W + (size_t)(k0 + bkr) * 512 + bn + bc);
        __syncthreads();

#pragma unroll
        for (int k = 0; k < 16; k++) {
            float a[8], b[4];
            *(float4*)(a)     = *(const float4*)&As[k][ty * 8];
            *(float4*)(a + 4) = *(const float4*)&As[k][ty * 8 + 4];
            *(float4*)(b)     = *(const float4*)&Bs[k][tx * 4];
#pragma unroll
            for (int j = 0; j < 8; j++)
#pragma unroll
                for (int l = 0; l < 4; l++) acc[j][l] = fmaf(a[j], b[l], acc[j][l]);
        }
        __syncthreads();
    }

    float4 bv = *(const float4*)(bias + bn + tx * 4);
    float bb[4] = {bv.x, bv.y, bv.z, bv.w};
    float* Hout = (bn < 256) ? g_xc : g_yc;
    const int cbase = ((bn < 256) ? bn : (bn - 256)) + tx * 4;
#pragma unroll
    for (int j = 0; j < 8; j++) {
        const int row = bm + ty * 8 + j;
        float4 o;
        o.x = acc[j][0] + bb[0]; o.y = acc[j][1] + bb[1];
        o.z = acc[j][2] + bb[2]; o.w = acc[j][3] + bb[3];
        *(float4*)(Hout + (size_t)row * 256 + cbase) = o;
    }
}

// ---------------- 2) polar init: (h1,h2) -> (xc,yc), accumulate per-chunk means ----------------
// grid (NCHUNK, B), 256 threads (= one d each), 64 rows per block.
__global__ __launch_bounds__(256) void k_polar() {
    const int b = blockIdx.y, chunk = blockIdx.x, d = threadIdx.x;
    const size_t base = ((size_t)b * SS + (size_t)chunk * 64) * DD + d;
    float sx = 0.0f, sy = 0.0f;
#pragma unroll 4
    for (int r = 0; r < 64; r++) {
        const size_t idx = base + (size_t)r * DD;
        const float h1 = g_xc[idx], h2 = g_yc[idx];
        const float rad = fabsf(h1) + 0.1f;
        float s, c;
        sincosf(PI_F * h2, &s, &c);
        const float X = rad * c, Y = rad * s;
        g_xc[idx] = X; g_yc[idx] = Y;
        sx += X; sy += Y;
    }
    const int kk = b * DD + d;
    g_xp[chunk * BD + kk] = sx;
    g_yp[chunk * BD + kk] = sy;
}

// ---------------- 3) per-layer tiny KAN MLPs on the [B,D] means ----------------
__global__ __launch_bounds__(256) void k_mlp(const float* __restrict__ mw1, const float* __restrict__ mb1,
                                             const float* __restrict__ mw2, const float* __restrict__ mb2,
                                             const float* __restrict__ pw1, const float* __restrict__ pb1,
                                             const float* __restrict__ pw2, const float* __restrict__ pb2,
                                             int layer) {
    __shared__ float w[260];
    const int t = threadIdx.x;
    if (t < 32)        w[t] = mw1[layer * 32 + t];
    else if (t < 64)   w[t] = mb1[layer * 32 + (t - 32)];
    else if (t < 96)   w[t] = mw2[layer * 32 + (t - 64)];
    else if (t < 160)  w[t] = pw1[layer * 64 + (t - 96)];    // [0..31]=row sin, [32..63]=row cos
    else if (t < 192)  w[t] = pb1[layer * 32 + (t - 160)];
    else               w[t] = pw2[layer * 64 + (t - 192)];   // interleaved [j*2 + {0,1}]
    if (t == 0) { w[256] = mb2[layer]; w[257] = pb2[2 * layer]; w[258] = pb2[2 * layer + 1]; }
    __syncthreads();

    const int k = blockIdx.x * 256 + t;   // (b,d) flat
    float xs = 0.0f, ys = 0.0f;
#pragma unroll
    for (int c = 0; c < NCHUNK; c++) { xs += g_xp[c * BD + k]; ys += g_yp[c * BD + k]; }
    const float xm = xs * (1.0f / SS), ym = ys * (1.0f / SS);

    const float ragg  = sqrtf(xm * xm + ym * ym + EPSF);
    const float thagg = atan2f(ym, xm);

    // magnitude MLP (1 -> 32 -> 1) in log space
    const float logr = logf(ragg + EPSF);
    float acc = 0.0f;
#pragma unroll
    for (int j = 0; j < 32; j++) {
        const float u = fmaf(logr, w[j], w[32 + j]);
        acc = fmaf(gelu_exact(u), w[64 + j], acc);
    }
    const float rt = expf(acc + w[256]);

    // phase MLP (2 -> 32 -> 2) on (sin, cos)
    float s0, c0;
    sincosf(thagg, &s0, &c0);
    float p0 = 0.0f, p1 = 0.0f;
#pragma unroll
    for (int j = 0; j < 32; j++) {
        const float u = fmaf(s0, w[96 + j], fmaf(c0, w[128 + j], w[160 + j]));
        const float g = gelu_exact(u);
        p0 = fmaf(g, w[192 + 2 * j],     p0);
        p1 = fmaf(g, w[192 + 2 * j + 1], p1);
    }
    p0 += w[257]; p1 += w[258];
    const float nrm = sqrtf(p0 * p0 + p1 * p1 + EPSF);
    const float tht = atan2f(p0 / nrm, p1 / nrm);
    float sd, cd;
    sincosf(tht, &sd, &cd);
    g_dx[k] = rt * cd;
    g_dy[k] = rt * sd;
}

// ---------------- 4) per-layer state update (Cartesian form, no per-element trig) ----------------
// xc' = (xc+dx)*sqrt(1+eps/q), q = (xc+dx)^2+(yc+dy)^2  ==  r_new*cos(theta_new) exactly.
// Also produces per-chunk partial sums for the NEXT layer's means (or r-sums on the last layer).
__global__ __launch_bounds__(256) void k_update(int last) {
    const int b = blockIdx.y, chunk = blockIdx.x, d = threadIdx.x;
    const int kk = b * DD + d;
    const float dxv = g_dx[kk], dyv = g_dy[kk];
    const size_t base = ((size_t)b * SS + (size_t)chunk * 64) * DD + d;
    float sx = 0.0f, sy = 0.0f;
    if (!last) {
#pragma unroll 4
        for (int r = 0; r < 64; r++) {
            const size_t idx = base + (size_t)r * DD;
            const float x = g_xc[idx] + dxv;
            const float y = g_yc[idx] + dyv;
            const float q = x * x + y * y;
            float xn, yn;
            if (q > 0.0f) {
                const float sc = sqrtf(q + EPSF) * rsqrtf(q);
                xn = x * sc; yn = y * sc;
            } else {                      // matches reference: r=sqrt(eps), theta=atan2(0,0)=0
                xn = sqrtf(EPSF); yn = 0.0f;
            }
            g_xc[idx] = xn; g_yc[idx] = yn;
            sx += xn; sy += yn;
        }
        g_xp[chunk * BD + kk] = sx;
        g_yp[chunk * BD + kk] = sy;
    } else {
#pragma unroll 4
        for (int r = 0; r < 64; r++) {
            const size_t idx = base + (size_t)r * DD;
            const float x = g_xc[idx] + dxv;
            const float y = g_yc[idx] + dyv;
            sx += sqrtf(x * x + y * y + EPSF);   // final r, pooled over S downstream
        }
        g_xp[chunk * BD + kk] = sx;
    }
}

// ---------------- 5) classifier: pooled [64,256] -> gelu(@W1+b1) -> @W2+b2 -> [64,1000] ----------------
__global__ __launch_bounds__(256) void k_cls(const float* __restrict__ w1, const float* __restrict__ b1,
                                             const float* __restrict__ w2, const float* __restrict__ b2,
                                             float* __restrict__ out) {
    __shared__ float p[DD];
    __shared__ float h[KANH];
    const int b = blockIdx.x, t = threadIdx.x;
    float s = 0.0f;
#pragma unroll
    for (int c = 0; c < NCHUNK; c++) s += g_xp[c * BD + b * DD + t];
    p[t] = s * (1.0f / SS);
    __syncthreads();
    if (t < KANH) {
        float a = b1[t];
        for (int d2 = 0; d2 < DD; d2++) a = fmaf(p[d2], w1[d2 * KANH + t], a);
        h[t] = gelu_exact(a);
    }
    __syncthreads();
    for (int c = t; c < NCLS; c += 256) {
        float a = b2[c];
#pragma unroll
        for (int j = 0; j < KANH; j++) a = fmaf(h[j], w2[j * NCLS + c], a);
        out[b * NCLS + c] = a;
    }
}

// ---------------- launch ----------------
extern "C" void kernel_launch(void* const* d_in, const int* in_sizes, int n_in,
                              void* d_out, int out_size) {
    const float* x   = (const float*)d_in[0];
    const float* ew  = (const float*)d_in[1];
    const float* eb  = (const float*)d_in[2];
    const float* mw1 = (const float*)d_in[3];
    const float* mb1 = (const float*)d_in[4];
    const float* mw2 = (const float*)d_in[5];
    const float* mb2 = (const float*)d_in[6];
    const float* pw1 = (const float*)d_in[7];
    const float* pb1 = (const float*)d_in[8];
    const float* pw2 = (const float*)d_in[9];
    const float* pb2 = (const float*)d_in[10];
    const float* cw1 = (const float*)d_in[11];
    const float* cb1 = (const float*)d_in[12];
    const float* cw2 = (const float*)d_in[13];
    const float* cb2 = (const float*)d_in[14];
    float* out = (float*)d_out;

    dim3 ggrid(512 / 64, (BB * SS) / 128);   // (8, 512)
    k_embed_gemm<<<ggrid, 256>>>(x, ew, eb);

    dim3 egrid(NCHUNK, BB);                  // (16, 64)
    k_polar<<<egrid, 256>>>();

    for (int i = 0; i < NLAYERS; i++) {
        k_mlp<<<BD / 256, 256>>>(mw1, mb1, mw2, mb2, pw1, pb1, pw2, pb2, i);
        k_update<<<egrid, 256>>>(i == NLAYERS - 1 ? 1 : 0);
    }

    k_cls<<<BB, 256>>>(cw1, cb1, cw2, cb2, out);
}

// round 9
// speedup vs baseline: 2.1345x; 2.1345x over previous
#include <cuda_runtime.h>
#include <math.h>

#define BB 64
#define SS 1024
#define DD 256
#define NLAYERS 8
#define KANH 32
#define NCLS 1000
#define EPSF 1e-8f
#define PI_F 3.14159265358979323846f
#define NCHUNK 16          /* S split into 16 chunks of 64 rows for deterministic partial sums */
#define BD (BB*DD)         /* 16384 */
#define WSTRIDE 260        /* per-layer weight block in shared */

// ---------------- persistent device scratch (no allocations allowed) ----------------
__device__ float g_xc[BB*SS*DD];      // xc0 (initial Cartesian state)
__device__ float g_yc[BB*SS*DD];      // yc0
__device__ float g_xp[NCHUNK*BD];     // per-chunk partial sums (xc0 sums, then final r sums)
__device__ float g_yp[NCHUNK*BD];     // per-chunk partial sums of yc0
__device__ float g_dx[BD];            // total accumulated DX over 8 layers
__device__ float g_dy[BD];            // total accumulated DY

__device__ __forceinline__ float gelu_exact(float v) {
    return 0.5f * v * (1.0f + erff(v * 0.70710678118654752440f));
}

// ---------------- 1) embed GEMM fused with polar init + chunk reduction ----------------
// Each block: 128 rows x 64 d-columns, computing BOTH h1 (W cols d) and h2 (W cols d+256).
// Epilogue: rad=|h1|+0.1, theta=pi*h2 -> (xc,yc) stored; per-chunk (64-row) sums of xc,yc
// written deterministically (each (chunk,d) owned by exactly one block/thread).
__global__ __launch_bounds__(256) void k_embed_fused(const float* __restrict__ A,
                                                     const float* __restrict__ W,
                                                     const float* __restrict__ bias) {
    __shared__ float As[16][128];   // transposed: As[k][m]  (reused as reduction scratch)
    __shared__ float Bs1[16][64];
    __shared__ float Bs2[16][64];

    const int tid  = threadIdx.x;
    const int bm   = blockIdx.y * 128;
    const int bn   = blockIdx.x * 64;
    const int tx   = tid & 15;          // 16 thread-cols * 4
    const int ty   = tid >> 4;          // 16 thread-rows * 8
    const int arow = tid >> 2;          // 0..63 (and +64)
    const int acol = (tid & 3) << 2;    // 0,4,8,12
    const int bkr  = tid >> 4;          // 0..15
    const int bc   = (tid & 15) << 2;   // 0..60

    float acc1[8][4], acc2[8][4];
#pragma unroll
    for (int j = 0; j < 8; j++)
#pragma unroll
        for (int l = 0; l < 4; l++) { acc1[j][l] = 0.0f; acc2[j][l] = 0.0f; }

    for (int k0 = 0; k0 < 256; k0 += 16) {
        float4 a0 = *(const float4*)(A + (size_t)(bm + arow)      * 256 + k0 + acol);
        float4 a1 = *(const float4*)(A + (size_t)(bm + arow + 64) * 256 + k0 + acol);
        As[acol + 0][arow]      = a0.x; As[acol + 1][arow]      = a0.y;
        As[acol + 2][arow]      = a0.z; As[acol + 3][arow]      = a0.w;
        As[acol + 0][arow + 64] = a1.x; As[acol + 1][arow + 64] = a1.y;
        As[acol + 2][arow + 64] = a1.z; As[acol + 3][arow + 64] = a1.w;
        *(float4*)&Bs1[bkr][bc] = *(const float4*)(W + (size_t)(k0 + bkr) * 512 + bn + bc);
        *(float4*)&Bs2[bkr][bc] = *(const float4*)(W + (size_t)(k0 + bkr) * 512 + bn + 256 + bc);
        __syncthreads();

#pragma unroll
        for (int k = 0; k < 16; k++) {
            float a[8], b1[4], b2[4];
            *(float4*)(a)      = *(const float4*)&As[k][ty * 8];
            *(float4*)(a + 4)  = *(const float4*)&As[k][ty * 8 + 4];
            *(float4*)(b1)     = *(const float4*)&Bs1[k][tx * 4];
            *(float4*)(b2)     = *(const float4*)&Bs2[k][tx * 4];
#pragma unroll
            for (int j = 0; j < 8; j++)
#pragma unroll
                for (int l = 0; l < 4; l++) {
                    acc1[j][l] = fmaf(a[j], b1[l], acc1[j][l]);
                    acc2[j][l] = fmaf(a[j], b2[l], acc2[j][l]);
                }
        }
        __syncthreads();
    }

    float4 bv1 = *(const float4*)(bias + bn + tx * 4);
    float4 bv2 = *(const float4*)(bias + 256 + bn + tx * 4);
    float bb1[4] = {bv1.x, bv1.y, bv1.z, bv1.w};
    float bb2[4] = {bv2.x, bv2.y, bv2.z, bv2.w};

    const int cbase = bn + tx * 4;
    float sx[4] = {0.f, 0.f, 0.f, 0.f}, sy[4] = {0.f, 0.f, 0.f, 0.f};

#pragma unroll
    for (int j = 0; j < 8; j++) {
        const int row = bm + ty * 8 + j;
        float4 ox, oy;
        float xs[4], ys[4];
#pragma unroll
        for (int l = 0; l < 4; l++) {
            const float h1 = acc1[j][l] + bb1[l];
            const float h2 = acc2[j][l] + bb2[l];
            const float rad = fabsf(h1) + 0.1f;
            float s, c;
            sincosf(PI_F * h2, &s, &c);
            xs[l] = rad * c; ys[l] = rad * s;
            sx[l] += xs[l];  sy[l] += ys[l];
        }
        ox.x = xs[0]; ox.y = xs[1]; ox.z = xs[2]; ox.w = xs[3];
        oy.x = ys[0]; oy.y = ys[1]; oy.z = ys[2]; oy.w = ys[3];
        *(float4*)(g_xc + (size_t)row * 256 + cbase) = ox;
        *(float4*)(g_yc + (size_t)row * 256 + cbase) = oy;
    }

    // Reduce sums over the 8 ty-rows of each 64-row chunk half (reuse As as scratch: 8KB)
    float* sred = (float*)As;
    __syncthreads();            // all main-loop reads of As done (last loop sync covers it too)
#pragma unroll
    for (int l = 0; l < 4; l++) { sred[tid * 8 + l] = sx[l]; sred[tid * 8 + 4 + l] = sy[l]; }
    __syncthreads();

    if ((ty & 7) == 0) {        // ty == 0 (chunk half 0) or ty == 8 (chunk half 1)
        const int b = bm >> 10;
        const int chunk = ((bm & 1023) >> 6) + (ty >> 3);
        float tx4[4] = {0.f, 0.f, 0.f, 0.f}, ty4[4] = {0.f, 0.f, 0.f, 0.f};
#pragma unroll
        for (int u = 0; u < 8; u++) {
            const int src = ((ty + u) * 16 + tx) * 8;
#pragma unroll
            for (int l = 0; l < 4; l++) { tx4[l] += sred[src + l]; ty4[l] += sred[src + 4 + l]; }
        }
#pragma unroll
        for (int l = 0; l < 4; l++) {
            g_xp[chunk * BD + b * DD + cbase + l] = tx4[l];
            g_yp[chunk * BD + b * DD + cbase + l] = ty4[l];
        }
    }
}

// ---------------- 2) all 8 KAN layers in ONE kernel (per-(b,d) independent chain) ----------------
// xm_i = xm_0 + sum_{j<i} dx_j (epsilon-renorm dropped: scale = 1 + O(5e-7)).
// Outputs total DX, DY per (b,d).
__global__ __launch_bounds__(256) void k_mlp_all(const float* __restrict__ mw1, const float* __restrict__ mb1,
                                                 const float* __restrict__ mw2, const float* __restrict__ mb2,
                                                 const float* __restrict__ pw1, const float* __restrict__ pb1,
                                                 const float* __restrict__ pw2, const float* __restrict__ pb2) {
    __shared__ float w[NLAYERS * WSTRIDE];
    const int t = threadIdx.x;

    for (int idx = t; idx < NLAYERS * WSTRIDE; idx += 256) {
        const int l = idx / WSTRIDE;
        const int o = idx - l * WSTRIDE;
        float v = 0.0f;
        if      (o < 32)  v = mw1[l * 32 + o];
        else if (o < 64)  v = mb1[l * 32 + (o - 32)];
        else if (o < 96)  v = mw2[l * 32 + (o - 64)];
        else if (o < 160) v = pw1[l * 64 + (o - 96)];     // [0..31]=sin row, [32..63]=cos row
        else if (o < 192) v = pb1[l * 32 + (o - 160)];
        else if (o < 256) v = pw2[l * 64 + (o - 192)];    // interleaved [j*2 + {0,1}]
        else if (o == 256) v = mb2[l];
        else if (o == 257) v = pb2[2 * l];
        else if (o == 258) v = pb2[2 * l + 1];
        w[idx] = v;
    }
    __syncthreads();

    const int k = blockIdx.x * 256 + t;   // (b,d) flat
    float xs = 0.0f, ys = 0.0f;
#pragma unroll
    for (int c = 0; c < NCHUNK; c++) { xs += g_xp[c * BD + k]; ys += g_yp[c * BD + k]; }
    float xm = xs * (1.0f / SS), ym = ys * (1.0f / SS);
    float DX = 0.0f, DY = 0.0f;

    for (int l = 0; l < NLAYERS; l++) {
        const float* wl = w + l * WSTRIDE;
        const float ragg  = sqrtf(xm * xm + ym * ym + EPSF);
        const float thagg = atan2f(ym, xm);

        // magnitude MLP (1 -> 32 -> 1) in log space
        const float logr = logf(ragg + EPSF);
        float acc = 0.0f;
#pragma unroll
        for (int j = 0; j < 32; j++) {
            const float u = fmaf(logr, wl[j], wl[32 + j]);
            acc = fmaf(gelu_exact(u), wl[64 + j], acc);
        }
        const float rt = expf(acc + wl[256]);

        // phase MLP (2 -> 32 -> 2) on (sin, cos)
        float s0, c0;
        sincosf(thagg, &s0, &c0);
        float p0 = 0.0f, p1 = 0.0f;
#pragma unroll
        for (int j = 0; j < 32; j++) {
            const float u = fmaf(s0, wl[96 + j], fmaf(c0, wl[128 + j], wl[160 + j]));
            const float g = gelu_exact(u);
            p0 = fmaf(g, wl[192 + 2 * j],     p0);
            p1 = fmaf(g, wl[192 + 2 * j + 1], p1);
        }
        p0 += wl[257]; p1 += wl[258];
        const float nrm = sqrtf(p0 * p0 + p1 * p1 + EPSF);
        const float tht = atan2f(p0 / nrm, p1 / nrm);
        float sd, cd;
        sincosf(tht, &sd, &cd);
        const float dx = rt * cd, dy = rt * sd;

        xm += dx; ym += dy;
        DX += dx; DY += dy;
    }
    g_dx[k] = DX;
    g_dy[k] = DY;
}

// ---------------- 3) final pass: r = sqrt((xc0+DX)^2 + (yc0+DY)^2 + eps), chunk sums ----------------
// grid (NCHUNK, B), 256 threads. Thread: d-group (float4) = t&63, row-subset = t>>6 (4-way).
__global__ __launch_bounds__(256) void k_final() {
    __shared__ float sh[4][64][4];
    const int b = blockIdx.y, chunk = blockIdx.x, t = threadIdx.x;
    const int c4 = t & 63, rsub = t >> 6;
    const int dbase = c4 * 4;

    const float4 dxv = *(const float4*)(g_dx + b * DD + dbase);
    const float4 dyv = *(const float4*)(g_dy + b * DD + dbase);

    float s[4] = {0.f, 0.f, 0.f, 0.f};
    const size_t rowbase = (size_t)b * SS + (size_t)chunk * 64;
#pragma unroll 4
    for (int i = 0; i < 16; i++) {
        const size_t idx = (rowbase + rsub + 4 * i) * DD + dbase;
        const float4 xv = *(const float4*)(g_xc + idx);
        const float4 yv = *(const float4*)(g_yc + idx);
        float x0 = xv.x + dxv.x, y0 = yv.x + dyv.x;
        float x1 = xv.y + dxv.y, y1 = yv.y + dyv.y;
        float x2 = xv.z + dxv.z, y2 = yv.z + dyv.z;
        float x3 = xv.w + dxv.w, y3 = yv.w + dyv.w;
        s[0] += sqrtf(fmaf(x0, x0, fmaf(y0, y0, EPSF)));
        s[1] += sqrtf(fmaf(x1, x1, fmaf(y1, y1, EPSF)));
        s[2] += sqrtf(fmaf(x2, x2, fmaf(y2, y2, EPSF)));
        s[3] += sqrtf(fmaf(x3, x3, fmaf(y3, y3, EPSF)));
    }
#pragma unroll
    for (int j = 0; j < 4; j++) sh[rsub][c4][j] = s[j];
    __syncthreads();
    if (rsub == 0) {
#pragma unroll
        for (int j = 0; j < 4; j++) {
            float tot = sh[0][c4][j] + sh[1][c4][j] + sh[2][c4][j] + sh[3][c4][j];
            g_xp[chunk * BD + b * DD + dbase + j] = tot;
        }
    }
}

// ---------------- 4) classifier: pooled [64,256] -> gelu(@W1+b1) -> @W2+b2 -> [64,1000] ----------------
__global__ __launch_bounds__(256) void k_cls(const float* __restrict__ w1, const float* __restrict__ b1,
                                             const float* __restrict__ w2, const float* __restrict__ b2,
                                             float* __restrict__ out) {
    __shared__ float p[DD];
    __shared__ float h[KANH];
    const int b = blockIdx.x, t = threadIdx.x;
    float s = 0.0f;
#pragma unroll
    for (int c = 0; c < NCHUNK; c++) s += g_xp[c * BD + b * DD + t];
    p[t] = s * (1.0f / SS);
    __syncthreads();
    if (t < KANH) {
        float a = b1[t];
        for (int d2 = 0; d2 < DD; d2++) a = fmaf(p[d2], w1[d2 * KANH + t], a);
        h[t] = gelu_exact(a);
    }
    __syncthreads();
    for (int c = t; c < NCLS; c += 256) {
        float a = b2[c];
#pragma unroll
        for (int j = 0; j < KANH; j++) a = fmaf(h[j], w2[j * NCLS + c], a);
        out[b * NCLS + c] = a;
    }
}

// ---------------- launch ----------------
extern "C" void kernel_launch(void* const* d_in, const int* in_sizes, int n_in,
                              void* d_out, int out_size) {
    const float* x   = (const float*)d_in[0];
    const float* ew  = (const float*)d_in[1];
    const float* eb  = (const float*)d_in[2];
    const float* mw1 = (const float*)d_in[3];
    const float* mb1 = (const float*)d_in[4];
    const float* mw2 = (const float*)d_in[5];
    const float* mb2 = (const float*)d_in[6];
    const float* pw1 = (const float*)d_in[7];
    const float* pb1 = (const float*)d_in[8];
    const float* pw2 = (const float*)d_in[9];
    const float* pb2 = (const float*)d_in[10];
    const float* cw1 = (const float*)d_in[11];
    const float* cb1 = (const float*)d_in[12];
    const float* cw2 = (const float*)d_in[13];
    const float* cb2 = (const float*)d_in[14];
    float* out = (float*)d_out;

    dim3 ggrid(DD / 64, (BB * SS) / 128);    // (4, 512) — each block does both h1/h2 halves
    k_embed_fused<<<ggrid, 256>>>(x, ew, eb);

    k_mlp_all<<<BD / 256, 256>>>(mw1, mb1, mw2, mb2, pw1, pb1, pw2, pb2);

    dim3 fgrid(NCHUNK, BB);                  // (16, 64)
    k_final<<<fgrid, 256>>>();

    k_cls<<<BB, 256>>>(cw1, cb1, cw2, cb2, out);
}